// round 1
// baseline (speedup 1.0000x reference)
#include <cuda_runtime.h>
#include <math.h>

#define LSEQ 2048
#define BSZ 2
#define HID 2560
#define NH 8
#define NKV 4
#define HD 256
#define WIN 512
#define QKVN 4096            // (8+4+4)*256
#define ML (BSZ*LSEQ)        // 4096
#define ODIM (NH*HD)         // 2048

// ---------------- scratch (device globals; no allocation allowed) ----------------
__device__ float g_QKV[(size_t)ML * QKVN];        // 64 MB: qkv projection output
__device__ float g_Qn[(size_t)BSZ * NH * LSEQ * HD];   // normed+roped q, (b,h,l,d)
__device__ float g_Kn[(size_t)BSZ * NKV * LSEQ * HD];  // normed+roped k, (b,h,l,d)
__device__ float g_O[(size_t)ML * ODIM];          // attention output, (b*l, h*256+d)
__device__ float g_cos[LSEQ * (HD/2)];
__device__ float g_sin[LSEQ * (HD/2)];

// ---------------- SGEMM: C[m, coff+n] = sum_k A[m*K+k] * B[n*K+k] ----------------
// 128x128 tile, BK=8, 256 threads, 8x8 per thread. M,N multiples of 128; K mult of 8.
__global__ void sgemm_nt(const float* __restrict__ A, const float* __restrict__ B,
                         float* __restrict__ C, int K, int ldc, int coff) {
    __shared__ float As[8][128];
    __shared__ float Bs[8][128];
    int t  = threadIdx.x;
    int bm = blockIdx.x, bn = blockIdx.y;
    int tx = t & 15, ty = t >> 4;
    int row = t >> 1, kc = (t & 1) * 4;

    const float* Ag = A + (size_t)(bm * 128 + row) * K + kc;
    const float* Bg = B + (size_t)(bn * 128 + row) * K + kc;

    float c[8][8];
    #pragma unroll
    for (int i = 0; i < 8; i++)
        #pragma unroll
        for (int j = 0; j < 8; j++) c[i][j] = 0.0f;

    for (int k0 = 0; k0 < K; k0 += 8) {
        float4 a = *(const float4*)(Ag + k0);
        float4 b = *(const float4*)(Bg + k0);
        As[kc + 0][row] = a.x; As[kc + 1][row] = a.y;
        As[kc + 2][row] = a.z; As[kc + 3][row] = a.w;
        Bs[kc + 0][row] = b.x; Bs[kc + 1][row] = b.y;
        Bs[kc + 2][row] = b.z; Bs[kc + 3][row] = b.w;
        __syncthreads();
        #pragma unroll
        for (int kk = 0; kk < 8; kk++) {
            float ar[8], br[8];
            *(float4*)(ar)     = *(const float4*)&As[kk][ty * 8];
            *(float4*)(ar + 4) = *(const float4*)&As[kk][ty * 8 + 4];
            *(float4*)(br)     = *(const float4*)&Bs[kk][tx * 8];
            *(float4*)(br + 4) = *(const float4*)&Bs[kk][tx * 8 + 4];
            #pragma unroll
            for (int i = 0; i < 8; i++)
                #pragma unroll
                for (int j = 0; j < 8; j++)
                    c[i][j] = fmaf(ar[i], br[j], c[i][j]);
        }
        __syncthreads();
    }
    #pragma unroll
    for (int i = 0; i < 8; i++) {
        float* Cg = C + (size_t)(bm * 128 + ty * 8 + i) * ldc + coff + bn * 128 + tx * 8;
        *(float4*)(Cg)     = make_float4(c[i][0], c[i][1], c[i][2], c[i][3]);
        *(float4*)(Cg + 4) = make_float4(c[i][4], c[i][5], c[i][6], c[i][7]);
    }
}

// ---------------- RoPE cos/sin table ----------------
__global__ void rope_table_kernel() {
    int i = threadIdx.x;          // 0..127
    int l = blockIdx.x;           // 0..2047
    double inv = exp(-(double)i * (log(10000.0) / 128.0));
    float arg = (float)l * (float)inv;
    g_cos[l * 128 + i] = cosf(arg);
    g_sin[l * 128 + i] = sinf(arg);
}

// ---------------- RMSNorm + RoPE for q (heads 0..7) and k (heads 8..11) ----------------
__global__ void normrope_kernel(const float* __restrict__ qnw, const float* __restrict__ knw) {
    int bl   = blockIdx.x;        // 0..4095
    int head = blockIdx.y;        // 0..11
    int d    = threadIdx.x;       // 0..255
    int l = bl & (LSEQ - 1);
    int b = bl >> 11;
    bool isq = head < NH;
    int col = isq ? head * HD + d : NH * HD + (head - NH) * HD + d;

    float x = g_QKV[(size_t)bl * QKVN + col];

    __shared__ float xs[HD];
    __shared__ float red[8];
    float ss = x * x;
    #pragma unroll
    for (int o = 16; o; o >>= 1) ss += __shfl_xor_sync(0xffffffffu, ss, o);
    if ((d & 31) == 0) red[d >> 5] = ss;
    __syncthreads();
    if (d < 8) {
        float v = red[d];
        #pragma unroll
        for (int o = 4; o; o >>= 1) v += __shfl_xor_sync(0xffu, v, o);
        if (d == 0) red[0] = v;
    }
    __syncthreads();
    float rs = rsqrtf(red[0] * (1.0f / HD) + 1e-6f);
    const float* w = isq ? qnw : knw;
    xs[d] = x * rs * (1.0f + w[d]);
    __syncthreads();

    int i = d & 127;
    float cs = g_cos[l * 128 + i];
    float sn = g_sin[l * 128 + i];
    float other = (d < 128) ? -xs[d + 128] : xs[d - 128];
    float out = xs[d] * cs + other * sn;

    if (isq) g_Qn[(((size_t)(b * NH + head)) * LSEQ + l) * HD + d] = out;
    else     g_Kn[(((size_t)(b * NKV + head - NH)) * LSEQ + l) * HD + d] = out;
}

// ---------------- attention over the last-512-key window ----------------
// Block: (qtile=64 queries) x (head) x (batch). 256 threads.
// Softcap bounds scores to (-50,50) -> fixed softmax shift of 50 (single pass).
#define QT 64
#define KT 32
#define QSTRIDE 260          // floats per Q row in smem (pad: 65 float4, odd -> 2-way max)
#define PSTRIDE 33           // floats per P row (kills same-bank striding)
#define ATTN_SMEM ((QT*QSTRIDE + KT*HD + KT*HD + QT*PSTRIDE) * 4)

__global__ void attn_kernel(const float* __restrict__ mask) {
    extern __shared__ float sm[];
    float* Qs = sm;                          // 64 x 260
    float* Ks = Qs + QT * QSTRIDE;           // 32 x 256
    float* Vs = Ks + KT * HD;                // 32 x 256
    float* Ps = Vs + KT * HD;                // 64 x 33

    int t  = threadIdx.x;
    int qt = blockIdx.x;    // 0..31
    int h  = blockIdx.y;    // 0..7
    int b  = blockIdx.z;    // 0..1
    int q0 = qt * QT;
    int kvh = h >> 1;
    const int S = LSEQ - WIN;   // 1536

    // load Q tile (pad rows to QSTRIDE)
    {
        const float4* Qg = (const float4*)(g_Qn + (((size_t)(b * NH + h)) * LSEQ + q0) * HD);
        float4* Qs4 = (float4*)Qs;
        #pragma unroll
        for (int i = 0; i < 16; i++) {
            int idx = t + 256 * i;              // 0..4095
            int r = idx >> 6, d4 = idx & 63;
            Qs4[r * (QSTRIDE / 4) + d4] = Qg[idx];
        }
    }

    // score mapping: thread computes q = qg + 16*i (i<4), k = kg*2 + j (j<2)
    int qg = t & 15;
    int kg = t >> 4;
    // AV mapping: thread owns q = qy + 16*m (m<4), d chunk dci*16 .. +15
    int qy  = t & 15;
    int dci = t >> 4;

    float4 acc[4][4];
    #pragma unroll
    for (int m = 0; m < 4; m++)
        #pragma unroll
        for (int i = 0; i < 4; i++) acc[m][i] = make_float4(0.f, 0.f, 0.f, 0.f);
    float den[4] = {0.f, 0.f, 0.f, 0.f};

    for (int kt0 = 0; kt0 < WIN; kt0 += KT) {
        __syncthreads();   // prev AV done reading Vs/Ps
        // K tile (contiguous rows in g_Kn)
        {
            const float4* Kg = (const float4*)(g_Kn + (((size_t)(b * NKV + kvh)) * LSEQ + S + kt0) * HD);
            float4* Ks4 = (float4*)Ks;
            #pragma unroll
            for (int i = 0; i < 8; i++) Ks4[t + 256 * i] = Kg[t + 256 * i];
        }
        // V tile (strided rows in g_QKV)
        {
            float4* Vs4 = (float4*)Vs;
            #pragma unroll
            for (int i = 0; i < 8; i++) {
                int idx = t + 256 * i;           // 0..2047
                int ki = idx >> 6, d4 = idx & 63;
                Vs4[idx] = *(const float4*)(g_QKV + ((size_t)(b * LSEQ + S + kt0 + ki)) * QKVN
                                            + (NH + NKV) * HD + kvh * HD + d4 * 4);
            }
        }
        __syncthreads();

        // ---- scores ----
        float sa[4][2];
        #pragma unroll
        for (int i = 0; i < 4; i++) { sa[i][0] = 0.f; sa[i][1] = 0.f; }
        const float4* K0 = (const float4*)(Ks + (kg * 2) * HD);
        const float4* K1 = (const float4*)(Ks + (kg * 2 + 1) * HD);
        const float4* Qs4 = (const float4*)Qs;
        #pragma unroll 4
        for (int d4 = 0; d4 < 64; d4++) {
            float4 k0 = K0[d4], k1 = K1[d4];
            #pragma unroll
            for (int i = 0; i < 4; i++) {
                float4 qv = Qs4[(qg + 16 * i) * (QSTRIDE / 4) + d4];
                sa[i][0] = fmaf(qv.x, k0.x, fmaf(qv.y, k0.y, fmaf(qv.z, k0.z, fmaf(qv.w, k0.w, sa[i][0]))));
                sa[i][1] = fmaf(qv.x, k1.x, fmaf(qv.y, k1.y, fmaf(qv.z, k1.z, fmaf(qv.w, k1.w, sa[i][1]))));
            }
        }
        #pragma unroll
        for (int i = 0; i < 4; i++)
            #pragma unroll
            for (int j = 0; j < 2; j++) {
                int qq = qg + 16 * i;
                int kk = kg * 2 + j;
                float s = sa[i][j] * 0.0625f;          // * HEAD_DIM^-0.5
                s = 50.0f * tanhf(s * 0.02f);          // softcap
                s += mask[(size_t)(q0 + qq) * LSEQ + (S + kt0 + kk)];
                Ps[qq * PSTRIDE + kk] = expf(s - 50.0f);
            }
        __syncthreads();

        // ---- P @ V ----
        #pragma unroll 2
        for (int kk = 0; kk < KT; kk++) {
            const float4* v4 = (const float4*)(Vs + kk * HD + dci * 16);
            float4 v0 = v4[0], v1 = v4[1], v2 = v4[2], v3 = v4[3];
            #pragma unroll
            for (int m = 0; m < 4; m++) {
                float p = Ps[(qy + 16 * m) * PSTRIDE + kk];
                den[m] += p;
                acc[m][0].x = fmaf(p, v0.x, acc[m][0].x);
                acc[m][0].y = fmaf(p, v0.y, acc[m][0].y);
                acc[m][0].z = fmaf(p, v0.z, acc[m][0].z);
                acc[m][0].w = fmaf(p, v0.w, acc[m][0].w);
                acc[m][1].x = fmaf(p, v1.x, acc[m][1].x);
                acc[m][1].y = fmaf(p, v1.y, acc[m][1].y);
                acc[m][1].z = fmaf(p, v1.z, acc[m][1].z);
                acc[m][1].w = fmaf(p, v1.w, acc[m][1].w);
                acc[m][2].x = fmaf(p, v2.x, acc[m][2].x);
                acc[m][2].y = fmaf(p, v2.y, acc[m][2].y);
                acc[m][2].z = fmaf(p, v2.z, acc[m][2].z);
                acc[m][2].w = fmaf(p, v2.w, acc[m][2].w);
                acc[m][3].x = fmaf(p, v3.x, acc[m][3].x);
                acc[m][3].y = fmaf(p, v3.y, acc[m][3].y);
                acc[m][3].z = fmaf(p, v3.z, acc[m][3].z);
                acc[m][3].w = fmaf(p, v3.w, acc[m][3].w);
            }
        }
    }

    #pragma unroll
    for (int m = 0; m < 4; m++) {
        float inv = 1.0f / den[m];
        float4* Og = (float4*)(g_O + ((size_t)(b * LSEQ + q0 + qy + 16 * m)) * ODIM
                               + h * HD + dci * 16);
        #pragma unroll
        for (int i = 0; i < 4; i++)
            Og[i] = make_float4(acc[m][i].x * inv, acc[m][i].y * inv,
                                acc[m][i].z * inv, acc[m][i].w * inv);
    }
}

// ---------------- launch ----------------
extern "C" void kernel_launch(void* const* d_in, const int* in_sizes, int n_in,
                              void* d_out, int out_size) {
    const float* x    = (const float*)d_in[0];
    const float* mask = (const float*)d_in[1];
    const float* q_w  = (const float*)d_in[2];
    const float* k_w  = (const float*)d_in[3];
    const float* v_w  = (const float*)d_in[4];
    const float* o_w  = (const float*)d_in[5];
    const float* qnw  = (const float*)d_in[6];
    const float* knw  = (const float*)d_in[7];
    float* out = (float*)d_out;

    float *qkv, *obuf;
    cudaGetSymbolAddress((void**)&qkv,  g_QKV);
    cudaGetSymbolAddress((void**)&obuf, g_O);

    cudaFuncSetAttribute(attn_kernel, cudaFuncAttributeMaxDynamicSharedMemorySize, ATTN_SMEM);

    rope_table_kernel<<<LSEQ, 128>>>();

    // QKV projections: C = X @ W^T  (M=4096, K=2560)
    sgemm_nt<<<dim3(ML / 128, (NH * HD) / 128), 256>>>(x, q_w, qkv, HID, QKVN, 0);
    sgemm_nt<<<dim3(ML / 128, (NKV * HD) / 128), 256>>>(x, k_w, qkv, HID, QKVN, NH * HD);
    sgemm_nt<<<dim3(ML / 128, (NKV * HD) / 128), 256>>>(x, v_w, qkv, HID, QKVN, (NH + NKV) * HD);

    normrope_kernel<<<dim3(ML, NH + NKV), 256>>>(qnw, knw);

    attn_kernel<<<dim3(LSEQ / QT, NH, BSZ), 256, ATTN_SMEM>>>(mask);

    // O projection: out = O @ o_w^T  (M=4096, N=2560, K=2048)
    sgemm_nt<<<dim3(ML / 128, HID / 128), 256>>>(obuf, o_w, out, ODIM, HID, 0);
}

// round 3
// speedup vs baseline: 1.0732x; 1.0732x over previous
#include <cuda_runtime.h>
#include <math.h>

#define LSEQ 2048
#define BSZ 2
#define HID 2560
#define NH 8
#define NKV 4
#define HD 256
#define WIN 512
#define QKVN 4096            // (8+4+4)*256
#define ML (BSZ*LSEQ)        // 4096
#define ODIM (NH*HD)         // 2048

typedef unsigned long long ull;

// packed f32x2 FMA: d = a*b + d  (2 fp32 lanes per instruction)
__device__ __forceinline__ void fma2(ull& d, ull a, ull b) {
    asm("fma.rn.f32x2 %0, %1, %2, %0;" : "+l"(d) : "l"(a), "l"(b));
}
__device__ __forceinline__ ull dup2(float x) {
    ull r;
    asm("mov.b64 %0, {%1, %1};" : "=l"(r) : "f"(x));
    return r;
}
__device__ __forceinline__ float lo2(ull v) { return ((float2*)&v)->x; }
__device__ __forceinline__ float hi2(ull v) { return ((float2*)&v)->y; }

// ---------------- scratch (device globals; no allocation allowed) ----------------
__device__ float g_QKV[(size_t)ML * QKVN];        // 64 MB: qkv projection output
__device__ float g_Qn[(size_t)BSZ * NH * LSEQ * HD];   // normed+roped q, (b,h,l,d)
__device__ float g_Kn[(size_t)BSZ * NKV * LSEQ * HD];  // normed+roped k, (b,h,l,d)
__device__ float g_O[(size_t)ML * ODIM];          // attention output, (b*l, h*256+d)
__device__ float g_cos[LSEQ * (HD/2)];
__device__ float g_sin[LSEQ * (HD/2)];

// ---------------- SGEMM: C[m, coff+n] = sum_k A[m*K+k] * B[n*K+k] ----------------
// 128x128 tile, BK=16, double-buffered smem, 256 threads, 8x8/thread via f32x2.
__global__ __launch_bounds__(256, 2)
void sgemm_nt(const float* __restrict__ A, const float* __restrict__ B,
              float* __restrict__ C, int K, int ldc, int coff) {
    __shared__ float As[2][16][128];
    __shared__ float Bs[2][16][128];
    int t  = threadIdx.x;
    int bm = blockIdx.x, bn = blockIdx.y;
    int tx = t & 15, ty = t >> 4;
    int row = t >> 1, kq = (t & 1) * 8;

    const float* Ag = A + (size_t)(bm * 128 + row) * K + kq;
    const float* Bg = B + (size_t)(bn * 128 + row) * K + kq;

    ull acc[8][4];   // [j=n][i2=m-pair]: C(m=ty*8+2*i2{+1}, n=tx*8+j)
    #pragma unroll
    for (int j = 0; j < 8; j++)
        #pragma unroll
        for (int i = 0; i < 4; i++) acc[j][i] = 0ull;

    float4 pa0 = *(const float4*)(Ag);
    float4 pa1 = *(const float4*)(Ag + 4);
    float4 pb0 = *(const float4*)(Bg);
    float4 pb1 = *(const float4*)(Bg + 4);
    {
        float av[8] = {pa0.x,pa0.y,pa0.z,pa0.w,pa1.x,pa1.y,pa1.z,pa1.w};
        float bv[8] = {pb0.x,pb0.y,pb0.z,pb0.w,pb1.x,pb1.y,pb1.z,pb1.w};
        #pragma unroll
        for (int c = 0; c < 8; c++) { As[0][kq+c][row] = av[c]; Bs[0][kq+c][row] = bv[c]; }
    }
    __syncthreads();

    int buf = 0;
    for (int k0 = 16; k0 <= K; k0 += 16) {
        bool more = k0 < K;
        if (more) {
            pa0 = *(const float4*)(Ag + k0);
            pa1 = *(const float4*)(Ag + k0 + 4);
            pb0 = *(const float4*)(Bg + k0);
            pb1 = *(const float4*)(Bg + k0 + 4);
        }
        #pragma unroll
        for (int kk = 0; kk < 16; kk++) {
            ulonglong2 a0 = *(const ulonglong2*)&As[buf][kk][ty * 8];
            ulonglong2 a1 = *(const ulonglong2*)&As[buf][kk][ty * 8 + 4];
            float4 b0 = *(const float4*)&Bs[buf][kk][tx * 8];
            float4 b1 = *(const float4*)&Bs[buf][kk][tx * 8 + 4];
            ull ap[4] = {a0.x, a0.y, a1.x, a1.y};
            float bf[8] = {b0.x,b0.y,b0.z,b0.w,b1.x,b1.y,b1.z,b1.w};
            #pragma unroll
            for (int j = 0; j < 8; j++) {
                ull bd = dup2(bf[j]);
                fma2(acc[j][0], ap[0], bd);
                fma2(acc[j][1], ap[1], bd);
                fma2(acc[j][2], ap[2], bd);
                fma2(acc[j][3], ap[3], bd);
            }
        }
        if (more) {
            int nb = buf ^ 1;
            float av[8] = {pa0.x,pa0.y,pa0.z,pa0.w,pa1.x,pa1.y,pa1.z,pa1.w};
            float bv[8] = {pb0.x,pb0.y,pb0.z,pb0.w,pb1.x,pb1.y,pb1.z,pb1.w};
            #pragma unroll
            for (int c = 0; c < 8; c++) { As[nb][kq+c][row] = av[c]; Bs[nb][kq+c][row] = bv[c]; }
        }
        __syncthreads();
        buf ^= 1;
    }

    #pragma unroll
    for (int i = 0; i < 8; i++) {
        float v[8];
        #pragma unroll
        for (int j = 0; j < 8; j++)
            v[j] = (i & 1) ? hi2(acc[j][i >> 1]) : lo2(acc[j][i >> 1]);
        float* Cg = C + (size_t)(bm * 128 + ty * 8 + i) * ldc + coff + bn * 128 + tx * 8;
        *(float4*)(Cg)     = make_float4(v[0], v[1], v[2], v[3]);
        *(float4*)(Cg + 4) = make_float4(v[4], v[5], v[6], v[7]);
    }
}

// ---------------- RoPE cos/sin table ----------------
__global__ void rope_table_kernel() {
    int i = threadIdx.x;          // 0..127
    int l = blockIdx.x;           // 0..2047
    double inv = exp(-(double)i * (log(10000.0) / 128.0));
    float arg = (float)l * (float)inv;
    g_cos[l * 128 + i] = cosf(arg);
    g_sin[l * 128 + i] = sinf(arg);
}

// ---------------- RMSNorm + RoPE for q (heads 0..7) and k (heads 8..11) ----------------
__global__ void normrope_kernel(const float* __restrict__ qnw, const float* __restrict__ knw) {
    int bl   = blockIdx.x;        // 0..4095
    int head = blockIdx.y;        // 0..11
    int d    = threadIdx.x;       // 0..255
    int l = bl & (LSEQ - 1);
    int b = bl >> 11;
    bool isq = head < NH;
    int col = isq ? head * HD + d : NH * HD + (head - NH) * HD + d;

    float x = g_QKV[(size_t)bl * QKVN + col];

    __shared__ float xs[HD];
    __shared__ float red[8];
    float ss = x * x;
    #pragma unroll
    for (int o = 16; o; o >>= 1) ss += __shfl_xor_sync(0xffffffffu, ss, o);
    if ((d & 31) == 0) red[d >> 5] = ss;
    __syncthreads();
    if (d < 8) {
        float v = red[d];
        #pragma unroll
        for (int o = 4; o; o >>= 1) v += __shfl_xor_sync(0xffu, v, o);
        if (d == 0) red[0] = v;
    }
    __syncthreads();
    float rs = rsqrtf(red[0] * (1.0f / HD) + 1e-6f);
    const float* w = isq ? qnw : knw;
    xs[d] = x * rs * (1.0f + w[d]);
    __syncthreads();

    int i = d & 127;
    float cs = g_cos[l * 128 + i];
    float sn = g_sin[l * 128 + i];
    float other = (d < 128) ? -xs[d + 128] : xs[d - 128];
    float out = xs[d] * cs + other * sn;

    if (isq) g_Qn[(((size_t)(b * NH + head)) * LSEQ + l) * HD + d] = out;
    else     g_Kn[(((size_t)(b * NKV + head - NH)) * LSEQ + l) * HD + d] = out;
}

// ---------------- attention over the last-512-key window ----------------
#define QT 64
#define KT 32
#define QSTRIDE 260          // floats per Q row in smem
#define PSTRIDE 33           // floats per P row
#define ATTN_SMEM ((QT*QSTRIDE + KT*HD + KT*HD + QT*PSTRIDE) * 4)

__global__ __launch_bounds__(256)
void attn_kernel(const float* __restrict__ mask) {
    extern __shared__ float sm[];
    float* Qs = sm;                          // 64 x 260
    float* Ks = Qs + QT * QSTRIDE;           // 32 x 256
    float* Vs = Ks + KT * HD;                // 32 x 256
    float* Ps = Vs + KT * HD;                // 64 x 33

    int t  = threadIdx.x;
    int qt = blockIdx.x;
    int h  = blockIdx.y;
    int b  = blockIdx.z;
    int q0 = qt * QT;
    int kvh = h >> 1;
    const int S = LSEQ - WIN;   // 1536

    // load Q tile
    {
        const float4* Qg = (const float4*)(g_Qn + (((size_t)(b * NH + h)) * LSEQ + q0) * HD);
        float4* Qs4 = (float4*)Qs;
        #pragma unroll
        for (int i = 0; i < 16; i++) {
            int idx = t + 256 * i;
            int r = idx >> 6, d4 = idx & 63;
            Qs4[r * (QSTRIDE / 4) + d4] = Qg[idx];
        }
    }

    int qg = t & 15;
    int kg = t >> 4;
    int qy  = t & 15;
    int dci = t >> 4;

    ull acc[4][8];       // [m][pair of d]: 16 floats per thread per m
    #pragma unroll
    for (int m = 0; m < 4; m++)
        #pragma unroll
        for (int i = 0; i < 8; i++) acc[m][i] = 0ull;
    float den[4] = {0.f, 0.f, 0.f, 0.f};

    for (int kt0 = 0; kt0 < WIN; kt0 += KT) {
        __syncthreads();
        // K tile
        {
            const float4* Kg = (const float4*)(g_Kn + (((size_t)(b * NKV + kvh)) * LSEQ + S + kt0) * HD);
            float4* Ks4 = (float4*)Ks;
            #pragma unroll
            for (int i = 0; i < 8; i++) Ks4[t + 256 * i] = Kg[t + 256 * i];
        }
        // V tile
        {
            float4* Vs4 = (float4*)Vs;
            #pragma unroll
            for (int i = 0; i < 8; i++) {
                int idx = t + 256 * i;
                int ki = idx >> 6, d4 = idx & 63;
                Vs4[idx] = *(const float4*)(g_QKV + ((size_t)(b * LSEQ + S + kt0 + ki)) * QKVN
                                            + (NH + NKV) * HD + kvh * HD + d4 * 4);
            }
        }
        __syncthreads();

        // ---- scores (f32x2 pairwise dot) ----
        ull sa[4][2];
        #pragma unroll
        for (int i = 0; i < 4; i++) { sa[i][0] = 0ull; sa[i][1] = 0ull; }
        const ulonglong2* K0 = (const ulonglong2*)(Ks + (kg * 2) * HD);
        const ulonglong2* K1 = (const ulonglong2*)(Ks + (kg * 2 + 1) * HD);
        const ulonglong2* Qs2 = (const ulonglong2*)Qs;
        #pragma unroll 4
        for (int d4 = 0; d4 < 64; d4++) {
            ulonglong2 k0 = K0[d4], k1 = K1[d4];
            #pragma unroll
            for (int i = 0; i < 4; i++) {
                ulonglong2 qv = Qs2[(qg + 16 * i) * (QSTRIDE / 4) + d4];
                fma2(sa[i][0], qv.x, k0.x);
                fma2(sa[i][0], qv.y, k0.y);
                fma2(sa[i][1], qv.x, k1.x);
                fma2(sa[i][1], qv.y, k1.y);
            }
        }
        #pragma unroll
        for (int i = 0; i < 4; i++)
            #pragma unroll
            for (int j = 0; j < 2; j++) {
                int qq = qg + 16 * i;
                int kk = kg * 2 + j;
                float s = (lo2(sa[i][j]) + hi2(sa[i][j])) * 0.0625f;   // HEAD_DIM^-0.5
                // softcap+softmax(shift 50): p = exp(mask - 100/(exp(0.04 s)+1))
                float e = __expf(s * 0.04f);
                float m = mask[(size_t)(q0 + qq) * LSEQ + (S + kt0 + kk)];
                Ps[qq * PSTRIDE + kk] = __expf(m - __fdividef(100.0f, e + 1.0f));
            }
        __syncthreads();

        // ---- P @ V (f32x2) ----
        #pragma unroll 2
        for (int kk = 0; kk < KT; kk++) {
            const ulonglong2* v2 = (const ulonglong2*)(Vs + kk * HD + dci * 16);
            ulonglong2 v0 = v2[0], v1 = v2[1];
            #pragma unroll
            for (int m = 0; m < 4; m++) {
                float p = Ps[(qy + 16 * m) * PSTRIDE + kk];
                den[m] += p;
                ull pd = dup2(p);
                fma2(acc[m][0], pd, v0.x);
                fma2(acc[m][1], pd, v0.y);
                fma2(acc[m][2], pd, v1.x);
                fma2(acc[m][3], pd, v1.y);
            }
            const ulonglong2* v2b = v2 + 2;
            ulonglong2 v2c = v2b[0], v3 = v2b[1];
            #pragma unroll
            for (int m = 0; m < 4; m++) {
                float p = Ps[(qy + 16 * m) * PSTRIDE + kk];
                ull pd = dup2(p);
                fma2(acc[m][4], pd, v2c.x);
                fma2(acc[m][5], pd, v2c.y);
                fma2(acc[m][6], pd, v3.x);
                fma2(acc[m][7], pd, v3.y);
            }
        }
    }

    #pragma unroll
    for (int m = 0; m < 4; m++) {
        float inv = 1.0f / den[m];
        float* Og = g_O + ((size_t)(b * LSEQ + q0 + qy + 16 * m)) * ODIM + h * HD + dci * 16;
        #pragma unroll
        for (int i = 0; i < 4; i++) {
            float4 o;
            o.x = lo2(acc[m][2*i])     * inv;
            o.y = hi2(acc[m][2*i])     * inv;
            o.z = lo2(acc[m][2*i + 1]) * inv;
            o.w = hi2(acc[m][2*i + 1]) * inv;
            *(float4*)(Og + i * 4) = o;
        }
    }
}

// ---------------- launch ----------------
extern "C" void kernel_launch(void* const* d_in, const int* in_sizes, int n_in,
                              void* d_out, int out_size) {
    const float* x    = (const float*)d_in[0];
    const float* mask = (const float*)d_in[1];
    const float* q_w  = (const float*)d_in[2];
    const float* k_w  = (const float*)d_in[3];
    const float* v_w  = (const float*)d_in[4];
    const float* o_w  = (const float*)d_in[5];
    const float* qnw  = (const float*)d_in[6];
    const float* knw  = (const float*)d_in[7];
    float* out = (float*)d_out;

    float *qkv, *obuf;
    cudaGetSymbolAddress((void**)&qkv,  g_QKV);
    cudaGetSymbolAddress((void**)&obuf, g_O);

    cudaFuncSetAttribute(attn_kernel, cudaFuncAttributeMaxDynamicSharedMemorySize, ATTN_SMEM);

    rope_table_kernel<<<LSEQ, 128>>>();

    // QKV projections: C = X @ W^T  (M=4096, K=2560)
    sgemm_nt<<<dim3(ML / 128, (NH * HD) / 128), 256>>>(x, q_w, qkv, HID, QKVN, 0);
    sgemm_nt<<<dim3(ML / 128, (NKV * HD) / 128), 256>>>(x, k_w, qkv, HID, QKVN, NH * HD);
    sgemm_nt<<<dim3(ML / 128, (NKV * HD) / 128), 256>>>(x, v_w, qkv, HID, QKVN, (NH + NKV) * HD);

    normrope_kernel<<<dim3(ML, NH + NKV), 256>>>(qnw, knw);

    attn_kernel<<<dim3(LSEQ / QT, NH, BSZ), 256, ATTN_SMEM>>>(mask);

    // O projection: out = O @ o_w^T  (M=4096, N=2560, K=2048)
    sgemm_nt<<<dim3(ML / 128, HID / 128), 256>>>(obuf, o_w, out, ODIM, HID, 0);
}

// round 5
// speedup vs baseline: 2.2710x; 2.1161x over previous
#include <cuda_runtime.h>
#include <cuda_bf16.h>
#include <math.h>
#include <stdint.h>

#define LSEQ 2048
#define BSZ 2
#define HID 2560
#define NH 8
#define NKV 4
#define HD 256
#define WIN 512
#define QKVN 4096            // (8+4+4)*256
#define ML (BSZ*LSEQ)        // 4096
#define ODIM (NH*HD)         // 2048

typedef unsigned long long ull;

// ---------------- f32x2 helpers (attention) ----------------
__device__ __forceinline__ void fma2(ull& d, ull a, ull b) {
    asm("fma.rn.f32x2 %0, %1, %2, %0;" : "+l"(d) : "l"(a), "l"(b));
}
__device__ __forceinline__ ull dup2(float x) {
    ull r;
    asm("mov.b64 %0, {%1, %1};" : "=l"(r) : "f"(x));
    return r;
}
__device__ __forceinline__ float lo2(ull v) { return ((float2*)&v)->x; }
__device__ __forceinline__ float hi2(ull v) { return ((float2*)&v)->y; }

// ---------------- mma.sync helpers (base sm_103 target: sm_80+ features only) ----------------
__device__ __forceinline__ uint32_t s2u(const void* p) {
    uint32_t a;
    asm("{ .reg .u64 t; cvta.to.shared.u64 t, %1; cvt.u32.u64 %0, t; }" : "=r"(a) : "l"(p));
    return a;
}
__device__ __forceinline__ void cp16(uint32_t dst, const void* src) {
    asm volatile("cp.async.cg.shared.global [%0], [%1], 16;" :: "r"(dst), "l"(src));
}
__device__ __forceinline__ void ldsm4(uint32_t* r, uint32_t addr) {
    asm volatile("ldmatrix.sync.aligned.m8n8.x4.shared.b16 {%0,%1,%2,%3}, [%4];"
        : "=r"(r[0]), "=r"(r[1]), "=r"(r[2]), "=r"(r[3]) : "r"(addr));
}
__device__ __forceinline__ void ldsm2(uint32_t* r, uint32_t addr) {
    asm volatile("ldmatrix.sync.aligned.m8n8.x2.shared.b16 {%0,%1}, [%2];"
        : "=r"(r[0]), "=r"(r[1]) : "r"(addr));
}
__device__ __forceinline__ void mma16816(float* c, const uint32_t* a, const uint32_t* b) {
    asm volatile("mma.sync.aligned.m16n8k16.row.col.f32.bf16.bf16.f32 "
        "{%0,%1,%2,%3}, {%4,%5,%6,%7}, {%8,%9}, {%0,%1,%2,%3};"
        : "+f"(c[0]), "+f"(c[1]), "+f"(c[2]), "+f"(c[3])
        : "r"(a[0]), "r"(a[1]), "r"(a[2]), "r"(a[3]), "r"(b[0]), "r"(b[1]));
}

// ---------------- scratch ----------------
__device__ float g_QKV[(size_t)ML * QKVN];
__device__ float g_Qn[(size_t)BSZ * NH * LSEQ * HD];
__device__ float g_Kn[(size_t)BSZ * NKV * LSEQ * HD];
__device__ float g_O[(size_t)ML * ODIM];
__device__ float g_cos[LSEQ * (HD/2)];
__device__ float g_sin[LSEQ * (HD/2)];
__device__ __align__(128) __nv_bfloat16 g_Xhi[(size_t)ML * HID];
__device__ __align__(128) __nv_bfloat16 g_Xlo[(size_t)ML * HID];
__device__ __align__(128) __nv_bfloat16 g_Whi[(size_t)QKVN * HID];
__device__ __align__(128) __nv_bfloat16 g_Wlo[(size_t)QKVN * HID];
__device__ __align__(128) __nv_bfloat16 g_Ohi[(size_t)ML * ODIM];
__device__ __align__(128) __nv_bfloat16 g_Olo[(size_t)ML * ODIM];
__device__ __align__(128) __nv_bfloat16 g_OWhi[(size_t)HID * ODIM];
__device__ __align__(128) __nv_bfloat16 g_OWlo[(size_t)HID * ODIM];

// ---------------- fp32 -> (hi,lo) bf16 split ----------------
__global__ void split_kernel(const float* __restrict__ s, __nv_bfloat16* __restrict__ hi,
                             __nv_bfloat16* __restrict__ lo, int n4) {
    int i = blockIdx.x * 256 + threadIdx.x;
    if (i >= n4) return;
    float4 v = ((const float4*)s)[i];
    float vv[4] = {v.x, v.y, v.z, v.w};
    __nv_bfloat16 h[4], l[4];
    #pragma unroll
    for (int j = 0; j < 4; j++) {
        h[j] = __float2bfloat16(vv[j]);
        l[j] = __float2bfloat16(vv[j] - __bfloat162float(h[j]));
    }
    ((__nv_bfloat162*)hi)[2*i]   = __halves2bfloat162(h[0], h[1]);
    ((__nv_bfloat162*)hi)[2*i+1] = __halves2bfloat162(h[2], h[3]);
    ((__nv_bfloat162*)lo)[2*i]   = __halves2bfloat162(l[0], l[1]);
    ((__nv_bfloat162*)lo)[2*i+1] = __halves2bfloat162(l[2], l[3]);
}

// ---------------- split-bf16 tensor-core GEMM (mma.sync m16n8k16) ----------------
// C[M,N] = A[M,K] @ B[N,K]^T in fp32 via 3-term bf16 split.
// Tile 128x128, BK=32, 8 warps (2m x 4n), warp tile 64x32, cp.async double-buffer.
#define BK 32
#define ASTR 80              // smem row stride in bytes (32 bf16 = 64B + 16B pad)
#define TILEB 10240          // one 128-row tile: 128*80
#define BUFB  40960          // 4 tiles (Ah,Al,Bh,Bl)
#define GEMM_SMEM (2*BUFB)

__global__ __launch_bounds__(256)
void gemm_bf16s(const __nv_bfloat16* __restrict__ Ahi, const __nv_bfloat16* __restrict__ Alo,
                const __nv_bfloat16* __restrict__ Bhi, const __nv_bfloat16* __restrict__ Blo,
                float* __restrict__ C, int K, int ldc) {
    extern __shared__ char smg[];
    uint32_t sbase = s2u(smg);
    int t = threadIdx.x, lane = t & 31, wid = t >> 5;
    int warp_m = wid >> 2, warp_n = wid & 3;
    int m0 = blockIdx.x * 128, n0 = blockIdx.y * 128;
    int NC = K / BK;

    float acc[4][4][4];
    #pragma unroll
    for (int mt = 0; mt < 4; mt++)
        #pragma unroll
        for (int nt = 0; nt < 4; nt++)
            #pragma unroll
            for (int q = 0; q < 4; q++) acc[mt][nt][q] = 0.0f;

    // per-thread load coords: c = t + 256*j -> row c>>2, 16B-chunk c&3
    int lrow = t >> 2, lkc = t & 3;

#define LOADCHUNK(i, buf) { \
        size_t k0 = (size_t)(i) * BK; \
        uint32_t dbase = sbase + (buf) * BUFB; \
        _Pragma("unroll") \
        for (int j = 0; j < 2; j++) { \
            int row = lrow + j * 64; \
            uint32_t dst = dbase + row * ASTR + lkc * 16; \
            size_t ga = (size_t)(m0 + row) * K + k0 + lkc * 8; \
            size_t gb = (size_t)(n0 + row) * K + k0 + lkc * 8; \
            cp16(dst,             Ahi + ga); \
            cp16(dst + TILEB,     Alo + ga); \
            cp16(dst + 2*TILEB,   Bhi + gb); \
            cp16(dst + 3*TILEB,   Blo + gb); \
        } \
        asm volatile("cp.async.commit_group;" ::: "memory"); \
    }

    LOADCHUNK(0, 0);

    uint32_t aoffs = (warp_m * 64 + (lane & 15)) * ASTR + (lane >> 4) * 16;
    uint32_t boffs = 2*TILEB + (warp_n * 32 + (lane & 7)) * ASTR + ((lane >> 3) & 1) * 16;

    for (int i = 0; i < NC; i++) {
        int buf = i & 1;
        if (i + 1 < NC) {
            LOADCHUNK(i + 1, buf ^ 1);
            asm volatile("cp.async.wait_group 1;" ::: "memory");
        } else {
            asm volatile("cp.async.wait_group 0;" ::: "memory");
        }
        __syncthreads();

        uint32_t ab = sbase + buf * BUFB + aoffs;
        uint32_t bb = sbase + buf * BUFB + boffs;
        #pragma unroll
        for (int ks = 0; ks < 2; ks++) {
            uint32_t ah[4][4], al[4][4], bh[4][2], bl[4][2];
            #pragma unroll
            for (int mt = 0; mt < 4; mt++) {
                uint32_t ad = ab + mt * (16 * ASTR) + ks * 32;
                ldsm4(ah[mt], ad);
                ldsm4(al[mt], ad + TILEB);
            }
            #pragma unroll
            for (int nt = 0; nt < 4; nt++) {
                uint32_t bd = bb + nt * (8 * ASTR) + ks * 32;
                ldsm2(bh[nt], bd);
                ldsm2(bl[nt], bd + TILEB);
            }
            #pragma unroll
            for (int mt = 0; mt < 4; mt++)
                #pragma unroll
                for (int nt = 0; nt < 4; nt++) {
                    mma16816(acc[mt][nt], ah[mt], bh[nt]);
                    mma16816(acc[mt][nt], al[mt], bh[nt]);
                    mma16816(acc[mt][nt], ah[mt], bl[nt]);
                }
        }
        __syncthreads();
    }

    // epilogue: lane l holds rows (l>>2, l>>2+8), cols (l&3)*2, +1 per tile
    #pragma unroll
    for (int mt = 0; mt < 4; mt++) {
        int r = m0 + warp_m * 64 + mt * 16 + (lane >> 2);
        #pragma unroll
        for (int nt = 0; nt < 4; nt++) {
            int cc = n0 + warp_n * 32 + nt * 8 + (lane & 3) * 2;
            *(float2*)(C + (size_t)r * ldc + cc)       = make_float2(acc[mt][nt][0], acc[mt][nt][1]);
            *(float2*)(C + (size_t)(r + 8) * ldc + cc) = make_float2(acc[mt][nt][2], acc[mt][nt][3]);
        }
    }
#undef LOADCHUNK
}

// ---------------- RoPE cos/sin table ----------------
__global__ void rope_table_kernel() {
    int i = threadIdx.x;
    int l = blockIdx.x;
    double inv = exp(-(double)i * (log(10000.0) / 128.0));
    float arg = (float)l * (float)inv;
    g_cos[l * 128 + i] = cosf(arg);
    g_sin[l * 128 + i] = sinf(arg);
}

// ---------------- RMSNorm + RoPE ----------------
__global__ void normrope_kernel(const float* __restrict__ qnw, const float* __restrict__ knw) {
    int bl   = blockIdx.x;
    int head = blockIdx.y;
    int d    = threadIdx.x;
    int l = bl & (LSEQ - 1);
    int b = bl >> 11;
    bool isq = head < NH;
    int col = isq ? head * HD + d : NH * HD + (head - NH) * HD + d;

    float x = g_QKV[(size_t)bl * QKVN + col];

    __shared__ float xs[HD];
    __shared__ float red[8];
    float ss = x * x;
    #pragma unroll
    for (int o = 16; o; o >>= 1) ss += __shfl_xor_sync(0xffffffffu, ss, o);
    if ((d & 31) == 0) red[d >> 5] = ss;
    __syncthreads();
    if (d < 8) {
        float v = red[d];
        #pragma unroll
        for (int o = 4; o; o >>= 1) v += __shfl_xor_sync(0xffu, v, o);
        if (d == 0) red[0] = v;
    }
    __syncthreads();
    float rs = rsqrtf(red[0] * (1.0f / HD) + 1e-6f);
    const float* w = isq ? qnw : knw;
    xs[d] = x * rs * (1.0f + w[d]);
    __syncthreads();

    int i = d & 127;
    float cs = g_cos[l * 128 + i];
    float sn = g_sin[l * 128 + i];
    float other = (d < 128) ? -xs[d + 128] : xs[d - 128];
    float out = xs[d] * cs + other * sn;

    if (isq) g_Qn[(((size_t)(b * NH + head)) * LSEQ + l) * HD + d] = out;
    else     g_Kn[(((size_t)(b * NKV + head - NH)) * LSEQ + l) * HD + d] = out;
}

// ---------------- attention (fp32, f32x2) ----------------
#define QT 64
#define KT 32
#define QSTRIDE 260
#define PSTRIDE 33
#define ATTN_SMEM ((QT*QSTRIDE + KT*HD + KT*HD + QT*PSTRIDE) * 4)

__global__ __launch_bounds__(256)
void attn_kernel(const float* __restrict__ mask) {
    extern __shared__ float sm[];
    float* Qs = sm;
    float* Ks = Qs + QT * QSTRIDE;
    float* Vs = Ks + KT * HD;
    float* Ps = Vs + KT * HD;

    int t  = threadIdx.x;
    int qt = blockIdx.x;
    int h  = blockIdx.y;
    int b  = blockIdx.z;
    int q0 = qt * QT;
    int kvh = h >> 1;
    const int S = LSEQ - WIN;

    {
        const float4* Qg = (const float4*)(g_Qn + (((size_t)(b * NH + h)) * LSEQ + q0) * HD);
        float4* Qs4 = (float4*)Qs;
        #pragma unroll
        for (int i = 0; i < 16; i++) {
            int idx = t + 256 * i;
            int r = idx >> 6, d4 = idx & 63;
            Qs4[r * (QSTRIDE / 4) + d4] = Qg[idx];
        }
    }

    int qg = t & 15;
    int kg = t >> 4;
    int qy  = t & 15;
    int dci = t >> 4;

    ull acc[4][8];
    #pragma unroll
    for (int m = 0; m < 4; m++)
        #pragma unroll
        for (int i = 0; i < 8; i++) acc[m][i] = 0ull;
    float den[4] = {0.f, 0.f, 0.f, 0.f};

    for (int kt0 = 0; kt0 < WIN; kt0 += KT) {
        __syncthreads();
        {
            const float4* Kg = (const float4*)(g_Kn + (((size_t)(b * NKV + kvh)) * LSEQ + S + kt0) * HD);
            float4* Ks4 = (float4*)Ks;
            #pragma unroll
            for (int i = 0; i < 8; i++) Ks4[t + 256 * i] = Kg[t + 256 * i];
        }
        {
            float4* Vs4 = (float4*)Vs;
            #pragma unroll
            for (int i = 0; i < 8; i++) {
                int idx = t + 256 * i;
                int ki = idx >> 6, d4 = idx & 63;
                Vs4[idx] = *(const float4*)(g_QKV + ((size_t)(b * LSEQ + S + kt0 + ki)) * QKVN
                                            + (NH + NKV) * HD + kvh * HD + d4 * 4);
            }
        }
        __syncthreads();

        ull sa[4][2];
        #pragma unroll
        for (int i = 0; i < 4; i++) { sa[i][0] = 0ull; sa[i][1] = 0ull; }
        const ulonglong2* K0 = (const ulonglong2*)(Ks + (kg * 2) * HD);
        const ulonglong2* K1 = (const ulonglong2*)(Ks + (kg * 2 + 1) * HD);
        const ulonglong2* Qs2 = (const ulonglong2*)Qs;
        #pragma unroll 4
        for (int d4 = 0; d4 < 64; d4++) {
            ulonglong2 k0 = K0[d4], k1 = K1[d4];
            #pragma unroll
            for (int i = 0; i < 4; i++) {
                ulonglong2 qv = Qs2[(qg + 16 * i) * (QSTRIDE / 4) + d4];
                fma2(sa[i][0], qv.x, k0.x);
                fma2(sa[i][0], qv.y, k0.y);
                fma2(sa[i][1], qv.x, k1.x);
                fma2(sa[i][1], qv.y, k1.y);
            }
        }
        #pragma unroll
        for (int i = 0; i < 4; i++)
            #pragma unroll
            for (int j = 0; j < 2; j++) {
                int qq = qg + 16 * i;
                int kk = kg * 2 + j;
                float s = (lo2(sa[i][j]) + hi2(sa[i][j])) * 0.0625f;
                float e = __expf(s * 0.04f);
                float m = mask[(size_t)(q0 + qq) * LSEQ + (S + kt0 + kk)];
                Ps[qq * PSTRIDE + kk] = __expf(m - __fdividef(100.0f, e + 1.0f));
            }
        __syncthreads();

        #pragma unroll 2
        for (int kk = 0; kk < KT; kk++) {
            const ulonglong2* v2 = (const ulonglong2*)(Vs + kk * HD + dci * 16);
            ulonglong2 v0 = v2[0], v1 = v2[1];
            #pragma unroll
            for (int m = 0; m < 4; m++) {
                float p = Ps[(qy + 16 * m) * PSTRIDE + kk];
                den[m] += p;
                ull pd = dup2(p);
                fma2(acc[m][0], pd, v0.x);
                fma2(acc[m][1], pd, v0.y);
                fma2(acc[m][2], pd, v1.x);
                fma2(acc[m][3], pd, v1.y);
            }
            const ulonglong2* v2b = v2 + 2;
            ulonglong2 v2c = v2b[0], v3 = v2b[1];
            #pragma unroll
            for (int m = 0; m < 4; m++) {
                float p = Ps[(qy + 16 * m) * PSTRIDE + kk];
                ull pd = dup2(p);
                fma2(acc[m][4], pd, v2c.x);
                fma2(acc[m][5], pd, v2c.y);
                fma2(acc[m][6], pd, v3.x);
                fma2(acc[m][7], pd, v3.y);
            }
        }
    }

    #pragma unroll
    for (int m = 0; m < 4; m++) {
        float inv = 1.0f / den[m];
        float* Og = g_O + ((size_t)(b * LSEQ + q0 + qy + 16 * m)) * ODIM + h * HD + dci * 16;
        #pragma unroll
        for (int i = 0; i < 4; i++) {
            float4 o;
            o.x = lo2(acc[m][2*i])     * inv;
            o.y = hi2(acc[m][2*i])     * inv;
            o.z = lo2(acc[m][2*i + 1]) * inv;
            o.w = hi2(acc[m][2*i + 1]) * inv;
            *(float4*)(Og + i * 4) = o;
        }
    }
}

// ---------------- launch ----------------
extern "C" void kernel_launch(void* const* d_in, const int* in_sizes, int n_in,
                              void* d_out, int out_size) {
    const float* x    = (const float*)d_in[0];
    const float* mask = (const float*)d_in[1];
    const float* q_w  = (const float*)d_in[2];
    const float* k_w  = (const float*)d_in[3];
    const float* v_w  = (const float*)d_in[4];
    const float* o_w  = (const float*)d_in[5];
    const float* qnw  = (const float*)d_in[6];
    const float* knw  = (const float*)d_in[7];
    float* out = (float*)d_out;

    float *qkv, *obuf;
    __nv_bfloat16 *xhi, *xlo, *whi, *wlo, *ohi, *olo, *owhi, *owlo;
    cudaGetSymbolAddress((void**)&qkv,  g_QKV);
    cudaGetSymbolAddress((void**)&obuf, g_O);
    cudaGetSymbolAddress((void**)&xhi,  g_Xhi);
    cudaGetSymbolAddress((void**)&xlo,  g_Xlo);
    cudaGetSymbolAddress((void**)&whi,  g_Whi);
    cudaGetSymbolAddress((void**)&wlo,  g_Wlo);
    cudaGetSymbolAddress((void**)&ohi,  g_Ohi);
    cudaGetSymbolAddress((void**)&olo,  g_Olo);
    cudaGetSymbolAddress((void**)&owhi, g_OWhi);
    cudaGetSymbolAddress((void**)&owlo, g_OWlo);

    cudaFuncSetAttribute(attn_kernel, cudaFuncAttributeMaxDynamicSharedMemorySize, ATTN_SMEM);
    cudaFuncSetAttribute(gemm_bf16s, cudaFuncAttributeMaxDynamicSharedMemorySize, GEMM_SMEM);

    rope_table_kernel<<<LSEQ, 128>>>();

    // splits: fp32 -> bf16 hi/lo
    {
        int n4 = (ML * HID) / 4;
        split_kernel<<<(n4 + 255) / 256, 256>>>(x, xhi, xlo, n4);
        n4 = (NH * HD * HID) / 4;   // q_w: 2048 x 2560
        split_kernel<<<(n4 + 255) / 256, 256>>>(q_w, whi, wlo, n4);
        n4 = (NKV * HD * HID) / 4;  // k_w, v_w: 1024 x 2560
        split_kernel<<<(n4 + 255) / 256, 256>>>(k_w, whi + (size_t)NH*HD*HID, wlo + (size_t)NH*HD*HID, n4);
        split_kernel<<<(n4 + 255) / 256, 256>>>(v_w, whi + (size_t)(NH+NKV)*HD*HID, wlo + (size_t)(NH+NKV)*HD*HID, n4);
        n4 = (HID * ODIM) / 4;      // o_w: 2560 x 2048
        split_kernel<<<(n4 + 255) / 256, 256>>>(o_w, owhi, owlo, n4);
    }

    // QKV projection: g_QKV[4096, 4096] = X @ W^T, K=2560
    gemm_bf16s<<<dim3(ML / 128, QKVN / 128), 256, GEMM_SMEM>>>(xhi, xlo, whi, wlo, qkv, HID, QKVN);

    normrope_kernel<<<dim3(ML, NH + NKV), 256>>>(qnw, knw);

    attn_kernel<<<dim3(LSEQ / QT, NH, BSZ), 256, ATTN_SMEM>>>(mask);

    // split attention output, then O projection: out[4096, 2560] = O @ o_w^T, K=2048
    {
        int n4 = (ML * ODIM) / 4;
        split_kernel<<<(n4 + 255) / 256, 256>>>(obuf, ohi, olo, n4);
    }
    gemm_bf16s<<<dim3(ML / 128, HID / 128), 256, GEMM_SMEM>>>(ohi, olo, owhi, owlo, out, ODIM, HID);
}

// round 6
// speedup vs baseline: 3.0880x; 1.3598x over previous
#include <cuda_runtime.h>
#include <cuda_bf16.h>
#include <math.h>
#include <stdint.h>

#define LSEQ 2048
#define BSZ 2
#define HID 2560
#define NH 8
#define NKV 4
#define HD 256
#define WIN 512
#define QKVN 4096            // (8+4+4)*256
#define ML (BSZ*LSEQ)        // 4096
#define ODIM (NH*HD)         // 2048

typedef unsigned long long ull;

// ---------------- mma.sync helpers (base sm_103 target) ----------------
__device__ __forceinline__ uint32_t s2u(const void* p) {
    uint32_t a;
    asm("{ .reg .u64 t; cvta.to.shared.u64 t, %1; cvt.u32.u64 %0, t; }" : "=r"(a) : "l"(p));
    return a;
}
__device__ __forceinline__ void cp16(uint32_t dst, const void* src) {
    asm volatile("cp.async.cg.shared.global [%0], [%1], 16;" :: "r"(dst), "l"(src));
}
__device__ __forceinline__ void ldsm4(uint32_t* r, uint32_t addr) {
    asm volatile("ldmatrix.sync.aligned.m8n8.x4.shared.b16 {%0,%1,%2,%3}, [%4];"
        : "=r"(r[0]), "=r"(r[1]), "=r"(r[2]), "=r"(r[3]) : "r"(addr));
}
__device__ __forceinline__ void ldsm4t(uint32_t* r, uint32_t addr) {
    asm volatile("ldmatrix.sync.aligned.m8n8.x4.trans.shared.b16 {%0,%1,%2,%3}, [%4];"
        : "=r"(r[0]), "=r"(r[1]), "=r"(r[2]), "=r"(r[3]) : "r"(addr));
}
__device__ __forceinline__ void ldsm2(uint32_t* r, uint32_t addr) {
    asm volatile("ldmatrix.sync.aligned.m8n8.x2.shared.b16 {%0,%1}, [%2];"
        : "=r"(r[0]), "=r"(r[1]) : "r"(addr));
}
__device__ __forceinline__ void mma16816(float* c, const uint32_t* a, const uint32_t* b) {
    asm volatile("mma.sync.aligned.m16n8k16.row.col.f32.bf16.bf16.f32 "
        "{%0,%1,%2,%3}, {%4,%5,%6,%7}, {%8,%9}, {%0,%1,%2,%3};"
        : "+f"(c[0]), "+f"(c[1]), "+f"(c[2]), "+f"(c[3])
        : "r"(a[0]), "r"(a[1]), "r"(a[2]), "r"(a[3]), "r"(b[0]), "r"(b[1]));
}
#define SW5(x) ((x) ^ (((x) >> 5) & 0x70))   // swizzle for 512B rows

// ---------------- scratch ----------------
__device__ float g_QKV[(size_t)ML * QKVN];
__device__ float g_O[(size_t)ML * ODIM];
__device__ float g_cos[LSEQ * (HD/2)];
__device__ float g_sin[LSEQ * (HD/2)];
__device__ __align__(128) __nv_bfloat16 g_Xhi[(size_t)ML * HID];
__device__ __align__(128) __nv_bfloat16 g_Xlo[(size_t)ML * HID];
__device__ __align__(128) __nv_bfloat16 g_Whi[(size_t)QKVN * HID];
__device__ __align__(128) __nv_bfloat16 g_Wlo[(size_t)QKVN * HID];
__device__ __align__(128) __nv_bfloat16 g_Ohi[(size_t)ML * ODIM];
__device__ __align__(128) __nv_bfloat16 g_Olo[(size_t)ML * ODIM];
__device__ __align__(128) __nv_bfloat16 g_OWhi[(size_t)HID * ODIM];
__device__ __align__(128) __nv_bfloat16 g_OWlo[(size_t)HID * ODIM];
// attention operands (bf16 hi/lo)
__device__ __align__(128) __nv_bfloat16 g_Qbh[(size_t)BSZ * NH * LSEQ * HD];
__device__ __align__(128) __nv_bfloat16 g_Qbl[(size_t)BSZ * NH * LSEQ * HD];
__device__ __align__(128) __nv_bfloat16 g_Kbh[(size_t)BSZ * NKV * LSEQ * HD];
__device__ __align__(128) __nv_bfloat16 g_Kbl[(size_t)BSZ * NKV * LSEQ * HD];
__device__ __align__(128) __nv_bfloat16 g_Vbh[(size_t)BSZ * NKV * WIN * HD];
__device__ __align__(128) __nv_bfloat16 g_Vbl[(size_t)BSZ * NKV * WIN * HD];

// ---------------- fp32 -> (hi,lo) bf16 split ----------------
__global__ void split_kernel(const float* __restrict__ s, __nv_bfloat16* __restrict__ hi,
                             __nv_bfloat16* __restrict__ lo, int n4) {
    int i = blockIdx.x * 256 + threadIdx.x;
    if (i >= n4) return;
    float4 v = ((const float4*)s)[i];
    float vv[4] = {v.x, v.y, v.z, v.w};
    __nv_bfloat16 h[4], l[4];
    #pragma unroll
    for (int j = 0; j < 4; j++) {
        h[j] = __float2bfloat16(vv[j]);
        l[j] = __float2bfloat16(vv[j] - __bfloat162float(h[j]));
    }
    ((__nv_bfloat162*)hi)[2*i]   = __halves2bfloat162(h[0], h[1]);
    ((__nv_bfloat162*)hi)[2*i+1] = __halves2bfloat162(h[2], h[3]);
    ((__nv_bfloat162*)lo)[2*i]   = __halves2bfloat162(l[0], l[1]);
    ((__nv_bfloat162*)lo)[2*i+1] = __halves2bfloat162(l[2], l[3]);
}

// ---------------- split-bf16 tensor-core GEMM ----------------
#define BK 32
#define ASTR 80
#define TILEB 10240
#define BUFB  40960
#define GEMM_SMEM (2*BUFB)

__global__ __launch_bounds__(256)
void gemm_bf16s(const __nv_bfloat16* __restrict__ Ahi, const __nv_bfloat16* __restrict__ Alo,
                const __nv_bfloat16* __restrict__ Bhi, const __nv_bfloat16* __restrict__ Blo,
                float* __restrict__ C, int K, int ldc) {
    extern __shared__ char smg[];
    uint32_t sbase = s2u(smg);
    int t = threadIdx.x, lane = t & 31, wid = t >> 5;
    int warp_m = wid >> 2, warp_n = wid & 3;
    int m0 = blockIdx.x * 128, n0 = blockIdx.y * 128;
    int NC = K / BK;

    float acc[4][4][4];
    #pragma unroll
    for (int mt = 0; mt < 4; mt++)
        #pragma unroll
        for (int nt = 0; nt < 4; nt++)
            #pragma unroll
            for (int q = 0; q < 4; q++) acc[mt][nt][q] = 0.0f;

    int lrow = t >> 2, lkc = t & 3;

#define LOADCHUNK(i, buf) { \
        size_t k0 = (size_t)(i) * BK; \
        uint32_t dbase = sbase + (buf) * BUFB; \
        _Pragma("unroll") \
        for (int j = 0; j < 2; j++) { \
            int row = lrow + j * 64; \
            uint32_t dst = dbase + row * ASTR + lkc * 16; \
            size_t ga = (size_t)(m0 + row) * K + k0 + lkc * 8; \
            size_t gb = (size_t)(n0 + row) * K + k0 + lkc * 8; \
            cp16(dst,             Ahi + ga); \
            cp16(dst + TILEB,     Alo + ga); \
            cp16(dst + 2*TILEB,   Bhi + gb); \
            cp16(dst + 3*TILEB,   Blo + gb); \
        } \
        asm volatile("cp.async.commit_group;" ::: "memory"); \
    }

    LOADCHUNK(0, 0);

    uint32_t aoffs = (warp_m * 64 + (lane & 15)) * ASTR + (lane >> 4) * 16;
    uint32_t boffs = 2*TILEB + (warp_n * 32 + (lane & 7)) * ASTR + ((lane >> 3) & 1) * 16;

    for (int i = 0; i < NC; i++) {
        int buf = i & 1;
        if (i + 1 < NC) {
            LOADCHUNK(i + 1, buf ^ 1);
            asm volatile("cp.async.wait_group 1;" ::: "memory");
        } else {
            asm volatile("cp.async.wait_group 0;" ::: "memory");
        }
        __syncthreads();

        uint32_t ab = sbase + buf * BUFB + aoffs;
        uint32_t bb = sbase + buf * BUFB + boffs;
        #pragma unroll
        for (int ks = 0; ks < 2; ks++) {
            uint32_t ah[4][4], al[4][4], bh[4][2], bl[4][2];
            #pragma unroll
            for (int mt = 0; mt < 4; mt++) {
                uint32_t ad = ab + mt * (16 * ASTR) + ks * 32;
                ldsm4(ah[mt], ad);
                ldsm4(al[mt], ad + TILEB);
            }
            #pragma unroll
            for (int nt = 0; nt < 4; nt++) {
                uint32_t bd = bb + nt * (8 * ASTR) + ks * 32;
                ldsm2(bh[nt], bd);
                ldsm2(bl[nt], bd + TILEB);
            }
            #pragma unroll
            for (int mt = 0; mt < 4; mt++)
                #pragma unroll
                for (int nt = 0; nt < 4; nt++) {
                    mma16816(acc[mt][nt], ah[mt], bh[nt]);
                    mma16816(acc[mt][nt], al[mt], bh[nt]);
                    mma16816(acc[mt][nt], ah[mt], bl[nt]);
                }
        }
        __syncthreads();
    }

    #pragma unroll
    for (int mt = 0; mt < 4; mt++) {
        int r = m0 + warp_m * 64 + mt * 16 + (lane >> 2);
        #pragma unroll
        for (int nt = 0; nt < 4; nt++) {
            int cc = n0 + warp_n * 32 + nt * 8 + (lane & 3) * 2;
            *(float2*)(C + (size_t)r * ldc + cc)       = make_float2(acc[mt][nt][0], acc[mt][nt][1]);
            *(float2*)(C + (size_t)(r + 8) * ldc + cc) = make_float2(acc[mt][nt][2], acc[mt][nt][3]);
        }
    }
#undef LOADCHUNK
}

// ---------------- RoPE cos/sin table ----------------
__global__ void rope_table_kernel() {
    int i = threadIdx.x;
    int l = blockIdx.x;
    double inv = exp(-(double)i * (log(10000.0) / 128.0));
    float arg = (float)l * (float)inv;
    g_cos[l * 128 + i] = cosf(arg);
    g_sin[l * 128 + i] = sinf(arg);
}

// ---------------- RMSNorm + RoPE -> bf16 hi/lo ----------------
__global__ void normrope_kernel(const float* __restrict__ qnw, const float* __restrict__ knw) {
    int bl   = blockIdx.x;
    int head = blockIdx.y;
    int d    = threadIdx.x;
    int l = bl & (LSEQ - 1);
    int b = bl >> 11;
    bool isq = head < NH;
    int col = isq ? head * HD + d : NH * HD + (head - NH) * HD + d;

    float x = g_QKV[(size_t)bl * QKVN + col];

    __shared__ float xs[HD];
    __shared__ float red[8];
    float ss = x * x;
    #pragma unroll
    for (int o = 16; o; o >>= 1) ss += __shfl_xor_sync(0xffffffffu, ss, o);
    if ((d & 31) == 0) red[d >> 5] = ss;
    __syncthreads();
    if (d < 8) {
        float v = red[d];
        #pragma unroll
        for (int o = 4; o; o >>= 1) v += __shfl_xor_sync(0xffu, v, o);
        if (d == 0) red[0] = v;
    }
    __syncthreads();
    float rs = rsqrtf(red[0] * (1.0f / HD) + 1e-6f);
    const float* w = isq ? qnw : knw;
    xs[d] = x * rs * (1.0f + w[d]);
    __syncthreads();

    int i = d & 127;
    float cs = g_cos[l * 128 + i];
    float sn = g_sin[l * 128 + i];
    float other = (d < 128) ? -xs[d + 128] : xs[d - 128];
    float out = xs[d] * cs + other * sn;

    __nv_bfloat16 hi = __float2bfloat16(out);
    __nv_bfloat16 lo = __float2bfloat16(out - __bfloat162float(hi));
    if (isq) {
        size_t base = (((size_t)(b * NH + head)) * LSEQ + l) * HD + d;
        g_Qbh[base] = hi; g_Qbl[base] = lo;
    } else {
        size_t base = (((size_t)(b * NKV + head - NH)) * LSEQ + l) * HD + d;
        g_Kbh[base] = hi; g_Kbl[base] = lo;
    }
}

// ---------------- V window split: g_QKV V-cols -> (b,kvh,li,d) bf16 hi/lo ----------------
__global__ void vsplit_kernel() {
    int bl = blockIdx.x;              // 0..BSZ*WIN-1
    int b  = bl >> 9;
    int li = bl & (WIN - 1);
    int l  = (LSEQ - WIN) + li;
    int d  = threadIdx.x;             // 0..255
    #pragma unroll
    for (int kvh = 0; kvh < NKV; kvh++) {
        float v = g_QKV[((size_t)(b * LSEQ + l)) * QKVN + (NH + NKV) * HD + kvh * HD + d];
        __nv_bfloat16 hi = __float2bfloat16(v);
        __nv_bfloat16 lo = __float2bfloat16(v - __bfloat162float(hi));
        size_t base = (((size_t)(b * NKV + kvh)) * WIN + li) * HD + d;
        g_Vbh[base] = hi; g_Vbl[base] = lo;
    }
}

// ---------------- tensor-core attention ----------------
// Block: 64 queries x 1 head. 8 warps: QK role (qw=w>>1, kw=w&1), PV role (qw, dw=w&1).
// KT=32 key tiles, double-buffered K/V. 3-term bf16 split on QK and PV.
#define AQ 64
#define AK 32
#define NT16 (WIN/AK)         // 16 tiles
// smem byte offsets
#define SQH 0
#define SQL 32768
#define SKH 65536             // + buf*16384
#define SKL 98304
#define SVH 131072
#define SVL 163840
#define SPH 196608
#define SPL 201728
#define SDEN 206848
#define ATTN_SMEM 207104

__global__ __launch_bounds__(256, 1)
void attn_mma(const float* __restrict__ mask) {
    extern __shared__ char sm8[];
    uint32_t sb = s2u(sm8);
    int t = threadIdx.x, lane = t & 31, w = t >> 5;
    int qw = w >> 1, kw = w & 1, dw = w & 1;
    int q0 = blockIdx.x * AQ;
    int h  = blockIdx.y;
    int b  = blockIdx.z;
    int kvh = h >> 1;
    const int S = LSEQ - WIN;

    if (t < AQ) *(float*)(sm8 + SDEN + t * 4) = 0.0f;

    // ---- Q tile load (64 x 256 bf16, hi+lo), swizzled 512B rows ----
    {
        const __nv_bfloat16* Qh = g_Qbh + (((size_t)(b * NH + h)) * LSEQ + q0) * HD;
        const __nv_bfloat16* Ql = g_Qbl + (((size_t)(b * NH + h)) * LSEQ + q0) * HD;
        #pragma unroll
        for (int j = 0; j < 8; j++) {
            int idx = t + 256 * j;
            int row = idx >> 5, ch = idx & 31;
            uint32_t so = SW5(row * 512 + ch * 16);
            cp16(sb + SQH + so, Qh + row * HD + ch * 8);
            cp16(sb + SQL + so, Ql + row * HD + ch * 8);
        }
        asm volatile("cp.async.commit_group;" ::: "memory");
    }

    const __nv_bfloat16* Kh = g_Kbh + (((size_t)(b * NKV + kvh)) * LSEQ + S) * HD;
    const __nv_bfloat16* Kl = g_Kbl + (((size_t)(b * NKV + kvh)) * LSEQ + S) * HD;
    const __nv_bfloat16* Vh = g_Vbh + ((size_t)(b * NKV + kvh)) * WIN * HD;
    const __nv_bfloat16* Vl = g_Vbl + ((size_t)(b * NKV + kvh)) * WIN * HD;

#define TLOAD(i, buf) { \
        size_t koff = (size_t)(i) * AK * HD; \
        _Pragma("unroll") \
        for (int j = 0; j < 4; j++) { \
            int idx = t + 256 * j; \
            int row = idx >> 5, ch = idx & 31; \
            uint32_t so = SW5(row * 512 + ch * 16); \
            size_t g = koff + (size_t)row * HD + ch * 8; \
            cp16(sb + SKH + (buf) * 16384 + so, Kh + g); \
            cp16(sb + SKL + (buf) * 16384 + so, Kl + g); \
            cp16(sb + SVH + (buf) * 16384 + so, Vh + g); \
            cp16(sb + SVL + (buf) * 16384 + so, Vl + g); \
        } \
        asm volatile("cp.async.commit_group;" ::: "memory"); \
    }

    TLOAD(0, 0);

    float o[16][4];
    #pragma unroll
    for (int nt = 0; nt < 16; nt++)
        #pragma unroll
        for (int q = 0; q < 4; q++) o[nt][q] = 0.0f;
    float dreg[2] = {0.0f, 0.0f};

    int ra = qw * 16 + (lane >> 2);   // query rows ra, ra+8 owned by this lane

    for (int i = 0; i < NT16; i++) {
        int buf = i & 1;
        if (i + 1 < NT16) {
            TLOAD(i + 1, buf ^ 1);
            asm volatile("cp.async.wait_group 1;" ::: "memory");
        } else {
            asm volatile("cp.async.wait_group 0;" ::: "memory");
        }
        __syncthreads();

        // ---- QK^T (3-term) ----
        float s[2][4];
        #pragma unroll
        for (int nt = 0; nt < 2; nt++)
            #pragma unroll
            for (int q = 0; q < 4; q++) s[nt][q] = 0.0f;
        {
            int qrow = qw * 16 + (lane & 15);
            int krow = kw * 16 + (lane & 7) + ((lane >> 4) << 3);
            #pragma unroll
            for (int ks = 0; ks < 16; ks++) {
                uint32_t ah[4], al[4], bh[4], bl[4];
                uint32_t qa = sb + SQH + SW5(qrow * 512 + ks * 32 + ((lane >> 4) << 4));
                ldsm4(ah, qa);
                ldsm4(al, qa + (SQL - SQH));
                uint32_t ka = sb + SKH + buf * 16384 +
                              SW5(krow * 512 + ks * 32 + (((lane >> 3) & 1) << 4));
                ldsm4(bh, ka);
                ldsm4(bl, ka + (SKL - SKH));
                mma16816(s[0], ah, bh);
                mma16816(s[0], al, bh);
                mma16816(s[0], ah, bl);
                mma16816(s[1], ah, bh + 2);
                mma16816(s[1], al, bh + 2);
                mma16816(s[1], ah, bl + 2);
            }
        }

        // ---- softcap + exp(shift 50) + split to bf16, store P ----
        #pragma unroll
        for (int nt = 0; nt < 2; nt++) {
            int kb = kw * 16 + nt * 8 + (lane & 3) * 2;
            int gk = S + i * AK + kb;
            #pragma unroll
            for (int half = 0; half < 2; half++) {
                int row = ra + half * 8;
                float2 mk = *(const float2*)(mask + (size_t)(q0 + row) * LSEQ + gk);
                float v0 = s[nt][half * 2]     * 0.0625f;
                float v1 = s[nt][half * 2 + 1] * 0.0625f;
                float e0 = __expf(v0 * 0.04f);
                float e1 = __expf(v1 * 0.04f);
                float p0 = __expf(mk.x - __fdividef(100.0f, e0 + 1.0f));
                float p1 = __expf(mk.y - __fdividef(100.0f, e1 + 1.0f));
                dreg[half] += p0 + p1;
                __nv_bfloat16 h0 = __float2bfloat16(p0);
                __nv_bfloat16 h1 = __float2bfloat16(p1);
                __nv_bfloat16 l0 = __float2bfloat16(p0 - __bfloat162float(h0));
                __nv_bfloat16 l1 = __float2bfloat16(p1 - __bfloat162float(h1));
                *(__nv_bfloat162*)(sm8 + SPH + row * 80 + kb * 2) = __halves2bfloat162(h0, h1);
                *(__nv_bfloat162*)(sm8 + SPL + row * 80 + kb * 2) = __halves2bfloat162(l0, l1);
            }
        }
        __syncthreads();

        // ---- P @ V (3-term) ----
        {
            int prow = qw * 16 + (lane & 15);
            int vrowb = (lane & 7) + (((lane >> 3) & 1) << 3);
            #pragma unroll
            for (int ks2 = 0; ks2 < 2; ks2++) {
                uint32_t pah[4], pal[4];
                uint32_t pa = sb + SPH + prow * 80 + ks2 * 32 + ((lane >> 4) << 4);
                ldsm4(pah, pa);
                ldsm4(pal, pa + (SPL - SPH));
                #pragma unroll
                for (int ntp = 0; ntp < 8; ntp++) {
                    uint32_t bvh[4], bvl[4];
                    uint32_t va = sb + SVH + buf * 16384 +
                        SW5((ks2 * 16 + vrowb) * 512 + dw * 256 + ntp * 32 + ((lane >> 4) << 4));
                    ldsm4t(bvh, va);
                    ldsm4t(bvl, va + (SVL - SVH));
                    mma16816(o[2 * ntp],     pah, bvh);
                    mma16816(o[2 * ntp],     pal, bvh);
                    mma16816(o[2 * ntp],     pah, bvl);
                    mma16816(o[2 * ntp + 1], pah, bvh + 2);
                    mma16816(o[2 * ntp + 1], pal, bvh + 2);
                    mma16816(o[2 * ntp + 1], pah, bvl + 2);
                }
            }
        }
        __syncthreads();
    }

    // ---- flush den (sum across quad lanes, then across the 2 k-warps) ----
    {
        float* denp = (float*)(sm8 + SDEN);
        #pragma unroll
        for (int half = 0; half < 2; half++) {
            float v = dreg[half];
            v += __shfl_xor_sync(0xffffffffu, v, 1);
            v += __shfl_xor_sync(0xffffffffu, v, 2);
            if ((lane & 3) == 0) atomicAdd(denp + ra + half * 8, v);
        }
    }
    __syncthreads();

    // ---- output: o / den ----
    {
        float inv0 = 1.0f / *(float*)(sm8 + SDEN + ra * 4);
        float inv1 = 1.0f / *(float*)(sm8 + SDEN + (ra + 8) * 4);
        #pragma unroll
        for (int nt = 0; nt < 16; nt++) {
            int gcol = h * HD + dw * 128 + nt * 8 + (lane & 3) * 2;
            float* O0 = g_O + ((size_t)(b * LSEQ + q0 + ra)) * ODIM + gcol;
            float* O1 = g_O + ((size_t)(b * LSEQ + q0 + ra + 8)) * ODIM + gcol;
            *(float2*)O0 = make_float2(o[nt][0] * inv0, o[nt][1] * inv0);
            *(float2*)O1 = make_float2(o[nt][2] * inv1, o[nt][3] * inv1);
        }
    }
#undef TLOAD
}

// ---------------- launch ----------------
extern "C" void kernel_launch(void* const* d_in, const int* in_sizes, int n_in,
                              void* d_out, int out_size) {
    const float* x    = (const float*)d_in[0];
    const float* mask = (const float*)d_in[1];
    const float* q_w  = (const float*)d_in[2];
    const float* k_w  = (const float*)d_in[3];
    const float* v_w  = (const float*)d_in[4];
    const float* o_w  = (const float*)d_in[5];
    const float* qnw  = (const float*)d_in[6];
    const float* knw  = (const float*)d_in[7];
    float* out = (float*)d_out;

    float *qkv, *obuf;
    __nv_bfloat16 *xhi, *xlo, *whi, *wlo, *ohi, *olo, *owhi, *owlo;
    cudaGetSymbolAddress((void**)&qkv,  g_QKV);
    cudaGetSymbolAddress((void**)&obuf, g_O);
    cudaGetSymbolAddress((void**)&xhi,  g_Xhi);
    cudaGetSymbolAddress((void**)&xlo,  g_Xlo);
    cudaGetSymbolAddress((void**)&whi,  g_Whi);
    cudaGetSymbolAddress((void**)&wlo,  g_Wlo);
    cudaGetSymbolAddress((void**)&ohi,  g_Ohi);
    cudaGetSymbolAddress((void**)&olo,  g_Olo);
    cudaGetSymbolAddress((void**)&owhi, g_OWhi);
    cudaGetSymbolAddress((void**)&owlo, g_OWlo);

    cudaFuncSetAttribute(gemm_bf16s, cudaFuncAttributeMaxDynamicSharedMemorySize, GEMM_SMEM);
    cudaFuncSetAttribute(attn_mma,   cudaFuncAttributeMaxDynamicSharedMemorySize, ATTN_SMEM);

    rope_table_kernel<<<LSEQ, 128>>>();

    // splits: fp32 -> bf16 hi/lo
    {
        int n4 = (ML * HID) / 4;
        split_kernel<<<(n4 + 255) / 256, 256>>>(x, xhi, xlo, n4);
        n4 = (NH * HD * HID) / 4;
        split_kernel<<<(n4 + 255) / 256, 256>>>(q_w, whi, wlo, n4);
        n4 = (NKV * HD * HID) / 4;
        split_kernel<<<(n4 + 255) / 256, 256>>>(k_w, whi + (size_t)NH*HD*HID, wlo + (size_t)NH*HD*HID, n4);
        split_kernel<<<(n4 + 255) / 256, 256>>>(v_w, whi + (size_t)(NH+NKV)*HD*HID, wlo + (size_t)(NH+NKV)*HD*HID, n4);
        n4 = (HID * ODIM) / 4;
        split_kernel<<<(n4 + 255) / 256, 256>>>(o_w, owhi, owlo, n4);
    }

    // QKV projection
    gemm_bf16s<<<dim3(ML / 128, QKVN / 128), 256, GEMM_SMEM>>>(xhi, xlo, whi, wlo, qkv, HID, QKVN);

    normrope_kernel<<<dim3(ML, NH + NKV), 256>>>(qnw, knw);
    vsplit_kernel<<<BSZ * WIN, 256>>>();

    attn_mma<<<dim3(LSEQ / AQ, NH, BSZ), 256, ATTN_SMEM>>>(mask);

    // O projection
    {
        int n4 = (ML * ODIM) / 4;
        split_kernel<<<(n4 + 255) / 256, 256>>>(obuf, ohi, olo, n4);
    }
    gemm_bf16s<<<dim3(ML / 128, HID / 128), 256, GEMM_SMEM>>>(ohi, olo, owhi, owlo, out, ODIM, HID);
}